// round 2
// baseline (speedup 1.0000x reference)
#include <cuda_runtime.h>

#define N 8192
#define NW 256          // 32-bit words per adjacency row
#define W_IMG 1920.0f
#define H_IMG 1080.0f

// ---- scratch (static device globals: no allocations allowed) ----
static __device__ unsigned int g_mask[N * NW];   // 8 MB adjacency bitmask (sorted order)
static __device__ float4       g_box[N];         // sorted, clipped boxes
static __device__ float        g_score[N];       // sorted scores
static __device__ unsigned int g_head[NW];       // head bitset
static __device__ int          g_cluster[N];
static __device__ int          g_counts[N];
static __device__ float        g_prob[N];
static __device__ int          g_y2bits[N];      // float-as-int for atomicMax (all y2 >= 0)
static __device__ int          g_first[N];

// ------------------------------------------------------------------
// K1: bitonic sort on 64-bit keys (desc score, asc index), then gather
//     clipped boxes + scores in sorted order; also init reduction arrays.
// ------------------------------------------------------------------
__global__ void sort_kernel(const float* __restrict__ boxes,
                            const float* __restrict__ scores) {
    extern __shared__ unsigned long long skey[];
    const int tid = threadIdx.x;

    for (int i = tid; i < N; i += blockDim.x) {
        unsigned int sb = __float_as_uint(scores[i]);   // scores > 0 => bits monotone
        skey[i] = ((unsigned long long)(~sb) << 32) | (unsigned int)i;
    }
    __syncthreads();

    for (int size = 2; size <= N; size <<= 1) {
        for (int stride = size >> 1; stride > 0; stride >>= 1) {
            for (int i = tid; i < N; i += blockDim.x) {
                int p = i ^ stride;
                if (p > i) {
                    bool up = ((i & size) == 0);
                    unsigned long long a = skey[i], b = skey[p];
                    if ((a > b) == up) { skey[i] = b; skey[p] = a; }
                }
            }
            __syncthreads();
        }
    }

    for (int i = tid; i < N; i += blockDim.x) {
        unsigned long long k = skey[i];
        int j = (int)(unsigned int)k;
        float sc = __uint_as_float(~(unsigned int)(k >> 32));
        float x1 = boxes[4 * j + 0], y1 = boxes[4 * j + 1];
        float x2 = boxes[4 * j + 2], y2 = boxes[4 * j + 3];
        x1 = fminf(fmaxf(x1, 0.0f), W_IMG);
        y1 = fminf(fmaxf(y1, 0.0f), H_IMG);
        x2 = fminf(fmaxf(x2, 0.0f), W_IMG);
        y2 = fminf(fmaxf(y2, 0.0f), H_IMG);
        g_box[i]   = make_float4(x1, y1, x2, y2);
        g_score[i] = sc;
        g_counts[i] = 0;
        g_prob[i]   = 0.0f;
        g_y2bits[i] = 0;          // float 0.0 bits; all y2 >= 0
        g_first[i]  = N;
    }
}

// ------------------------------------------------------------------
// K2: adjacency bitmask. Grid (4, 256): 2048 cols x 32 rows per block.
// Warp layout: lane = row, warp handles full words => shared broadcast.
// ------------------------------------------------------------------
__global__ void mask_kernel() {
    __shared__ float4 s_cols[2048];
    __shared__ float  s_ca[2048];
    const int tid = threadIdx.x;
    const int cbase = blockIdx.x * 2048;

    for (int k = tid; k < 2048; k += 256) {
        float4 cb = g_box[cbase + k];
        s_cols[k] = cb;
        s_ca[k] = ((cb.z - cb.x) + 1.0f) * ((cb.w - cb.y) + 1.0f);
    }
    const int r = blockIdx.y * 32 + (tid & 31);
    const float4 rb = g_box[r];
    const float ra = ((rb.z - rb.x) + 1.0f) * ((rb.w - rb.y) + 1.0f);
    __syncthreads();

    const int wq = tid >> 5;   // warp id: 0..7
#pragma unroll
    for (int k = 0; k < 8; k++) {
        int wl = wq + 8 * k;   // local word 0..63
        unsigned int bits = 0;
#pragma unroll 4
        for (int b = 0; b < 32; b++) {
            float4 cb = s_cols[wl * 32 + b];   // broadcast across warp
            float  ca = s_ca[wl * 32 + b];
            float ix1 = fmaxf(rb.x, cb.x);
            float iy1 = fmaxf(rb.y, cb.y);
            float ix2 = fminf(rb.z, cb.z);
            float iy2 = fminf(rb.w, cb.w);
            float iw = fmaxf((ix2 - ix1) + 1.0f, 0.0f);
            float ih = fmaxf((iy2 - iy1) + 1.0f, 0.0f);
            float inter = iw * ih;
            float denom = (ra + ca) - inter;          // area_i + area_j - inter
            float diff  = 2.0f * inter - denom;       // exact sign test vs 0.5
            bool adj;
            if (fabsf(diff) > 1e-6f * denom) adj = (diff > 0.0f);
            else adj = (__fdiv_rn(inter, denom) > 0.5f);  // replicate ref rounding
            bits |= (adj ? 1u : 0u) << b;
        }
        g_mask[r * NW + blockIdx.x * 64 + wl] = bits;
    }
}

// ------------------------------------------------------------------
// K3: serial head pass, 32 bits per chunk. Single block, 256 threads.
// Thread t owns remv word t. Thread W resolves chunk W's 32 bits
// serially; other threads speculatively prefetch candidate rows.
// ------------------------------------------------------------------
__global__ void head_kernel() {
    __shared__ unsigned int s_diag[32];
    __shared__ unsigned int s_hw;
    const int tid = threadIdx.x;
    unsigned int remv = 0;

    for (int W = 0; W < NW; W++) {
        unsigned int m[32];
        if (tid > W) {
#pragma unroll
            for (int b = 0; b < 32; b++)
                m[b] = g_mask[(W * 32 + b) * NW + tid];
        }
        if (tid < 32) s_diag[tid] = g_mask[(W * 32 + tid) * NW + W];
        __syncthreads();

        if (tid == W) {
            unsigned int sup = remv, hw = 0;
#pragma unroll 4
            for (int b = 0; b < 32; b++) {
                if (!((sup >> b) & 1u)) { hw |= 1u << b; sup |= s_diag[b]; }
            }
            remv = sup;
            s_hw = hw;
            g_head[W] = hw;
        }
        __syncthreads();

        unsigned int hw = s_hw;
        if (tid > W) {
#pragma unroll
            for (int b = 0; b < 32; b++)
                if (hw & (1u << b)) remv |= m[b];
        }
    }
}

// ------------------------------------------------------------------
// K4: cluster[j] = first set bit of (row[j] & heads); then pass-A atomics.
// ------------------------------------------------------------------
__global__ void cluster_kernel() {
    __shared__ unsigned int s_head[NW];
    const int tid = threadIdx.x;
    if (tid < NW) s_head[tid] = g_head[tid];
    __syncthreads();

    const int j = blockIdx.x * blockDim.x + tid;
    const unsigned int* row = &g_mask[j * NW];
    int c = j;
    for (int w = 0; w < NW; w++) {
        unsigned int v = row[w] & s_head[w];
        if (v) { c = w * 32 + (__ffs(v) - 1); break; }
    }
    g_cluster[j] = c;
    atomicAdd(&g_counts[c], 1);
    atomicAdd(&g_prob[c], g_score[j]);
    atomicMax(&g_y2bits[c], __float_as_int(g_box[j].w));   // y2 >= 0 => int order ok
}

// ------------------------------------------------------------------
// K5: first = segment_min over candidates (y2 >= segment max)
// ------------------------------------------------------------------
__global__ void first_kernel() {
    const int j = blockIdx.x * blockDim.x + threadIdx.x;
    const int c = g_cluster[j];
    float y2 = g_box[j].w;
    float m  = __int_as_float(g_y2bits[c]);
    if (y2 >= m) atomicMin(&g_first[c], j);
}

// ------------------------------------------------------------------
// K6: keep + output. out rows (N,5) float, then keep (N) as 0/1 float.
// ------------------------------------------------------------------
__global__ void out_kernel(float* __restrict__ out, int out_size,
                           const int* __restrict__ nm_ptr) {
    const int j = blockIdx.x * blockDim.x + threadIdx.x;
    const int nm = *nm_ptr;
    const int c = g_cluster[j];
    bool keep = (g_first[c] == j) &&
                ((float)g_counts[c] >= (float)nm / 3.0f);
    float4 bb = g_box[j];
    float so = g_prob[c] / (float)nm;
    float v0 = 0.0f, v1 = 0.0f, v2 = 0.0f, v3 = 0.0f, v4 = 0.0f;
    if (keep) { v0 = bb.x; v1 = bb.y; v2 = bb.z; v3 = bb.w; v4 = so; }
    out[5 * j + 0] = v0;
    out[5 * j + 1] = v1;
    out[5 * j + 2] = v2;
    out[5 * j + 3] = v3;
    out[5 * j + 4] = v4;
    if (out_size >= 6 * N)
        out[5 * N + j] = keep ? 1.0f : 0.0f;
}

// ------------------------------------------------------------------
extern "C" void kernel_launch(void* const* d_in, const int* in_sizes, int n_in,
                              void* d_out, int out_size) {
    const float* boxes  = (const float*)d_in[0];
    const float* scores = (const float*)d_in[1];
    const int*   nm     = (const int*)d_in[2];

    cudaFuncSetAttribute(sort_kernel,
                         cudaFuncAttributeMaxDynamicSharedMemorySize, 65536);

    sort_kernel<<<1, 1024, 65536>>>(boxes, scores);
    dim3 mgrid(4, 256);
    mask_kernel<<<mgrid, 256>>>();
    head_kernel<<<1, 256>>>();
    cluster_kernel<<<32, 256>>>();
    first_kernel<<<32, 256>>>();
    out_kernel<<<32, 256>>>((float*)d_out, out_size, nm);
}

// round 3
// speedup vs baseline: 1.3591x; 1.3591x over previous
#include <cuda_runtime.h>

#define N 8192
#define NW 256          // 32-bit words per adjacency row
#define W_IMG 1920.0f
#define H_IMG 1080.0f

// ---- scratch (static device globals: no allocations allowed) ----
static __device__ unsigned int g_mask[N * NW];   // 8 MB adjacency bitmask (sorted order)
static __device__ float4       g_box[N];         // sorted, clipped boxes
static __device__ float        g_score[N];       // sorted scores
static __device__ unsigned int g_head[NW];       // head bitset
static __device__ int          g_cluster[N];
static __device__ int          g_counts[N];
static __device__ float        g_prob[N];
static __device__ int          g_y2bits[N];      // float-as-int for atomicMax (all y2 >= 0)
static __device__ int          g_first[N];

// ------------------------------------------------------------------
// K1: bitonic sort on 64-bit keys (desc score, asc index), then gather
//     clipped boxes + scores in sorted order; also init reduction arrays.
// ------------------------------------------------------------------
__global__ void sort_kernel(const float* __restrict__ boxes,
                            const float* __restrict__ scores) {
    extern __shared__ unsigned long long skey[];
    const int tid = threadIdx.x;

    for (int i = tid; i < N; i += blockDim.x) {
        unsigned int sb = __float_as_uint(scores[i]);   // scores > 0 => bits monotone
        skey[i] = ((unsigned long long)(~sb) << 32) | (unsigned int)i;
    }
    __syncthreads();

    for (int size = 2; size <= N; size <<= 1) {
        for (int stride = size >> 1; stride > 0; stride >>= 1) {
            // N/2 compare-exchanges per stage; 1024 threads -> 4 each, no wasted lanes
            for (int t = tid; t < N / 2; t += blockDim.x) {
                int i = ((t & ~(stride - 1)) << 1) | (t & (stride - 1));
                int p = i + stride;
                bool up = ((i & size) == 0);
                unsigned long long a = skey[i], b = skey[p];
                if ((a > b) == up) { skey[i] = b; skey[p] = a; }
            }
            __syncthreads();
        }
    }

    for (int i = tid; i < N; i += blockDim.x) {
        unsigned long long k = skey[i];
        int j = (int)(unsigned int)k;
        float sc = __uint_as_float(~(unsigned int)(k >> 32));
        float x1 = boxes[4 * j + 0], y1 = boxes[4 * j + 1];
        float x2 = boxes[4 * j + 2], y2 = boxes[4 * j + 3];
        x1 = fminf(fmaxf(x1, 0.0f), W_IMG);
        y1 = fminf(fmaxf(y1, 0.0f), H_IMG);
        x2 = fminf(fmaxf(x2, 0.0f), W_IMG);
        y2 = fminf(fmaxf(y2, 0.0f), H_IMG);
        g_box[i]   = make_float4(x1, y1, x2, y2);
        g_score[i] = sc;
        g_counts[i] = 0;
        g_prob[i]   = 0.0f;
        g_y2bits[i] = 0;          // float 0.0 bits; all y2 >= 0
        g_first[i]  = N;
    }
}

// ------------------------------------------------------------------
// K2: adjacency bitmask. Grid (4, 256): 2048 cols x 32 rows per block.
// Warp layout: lane = row, warp handles full words => shared broadcast.
// ------------------------------------------------------------------
__global__ void mask_kernel() {
    __shared__ float4 s_cols[2048];
    __shared__ float  s_ca[2048];
    const int tid = threadIdx.x;
    const int cbase = blockIdx.x * 2048;

    for (int k = tid; k < 2048; k += 256) {
        float4 cb = g_box[cbase + k];
        s_cols[k] = cb;
        s_ca[k] = ((cb.z - cb.x) + 1.0f) * ((cb.w - cb.y) + 1.0f);
    }
    const int r = blockIdx.y * 32 + (tid & 31);
    const float4 rb = g_box[r];
    const float ra = ((rb.z - rb.x) + 1.0f) * ((rb.w - rb.y) + 1.0f);
    __syncthreads();

    const int wq = tid >> 5;   // warp id: 0..7
#pragma unroll
    for (int k = 0; k < 8; k++) {
        int wl = wq + 8 * k;   // local word 0..63
        unsigned int bits = 0;
#pragma unroll 4
        for (int b = 0; b < 32; b++) {
            float4 cb = s_cols[wl * 32 + b];   // broadcast across warp
            float  ca = s_ca[wl * 32 + b];
            float ix1 = fmaxf(rb.x, cb.x);
            float iy1 = fmaxf(rb.y, cb.y);
            float ix2 = fminf(rb.z, cb.z);
            float iy2 = fminf(rb.w, cb.w);
            float iw = fmaxf((ix2 - ix1) + 1.0f, 0.0f);
            float ih = fmaxf((iy2 - iy1) + 1.0f, 0.0f);
            float inter = iw * ih;
            float denom = (ra + ca) - inter;          // area_i + area_j - inter
            float diff  = 2.0f * inter - denom;       // exact sign test vs 0.5
            bool adj;
            if (fabsf(diff) > 1e-6f * denom) adj = (diff > 0.0f);
            else adj = (__fdiv_rn(inter, denom) > 0.5f);  // replicate ref rounding
            bits |= (adj ? 1u : 0u) << b;
        }
        g_mask[r * NW + blockIdx.x * 64 + wl] = bits;
    }
}

// ------------------------------------------------------------------
// K3: serial head pass, 32 bits per chunk. Single block, 256 threads.
// Software-pipelined: chunk W+1's rows are prefetched into registers
// while chunk W is resolved. Thread t owns remv word t. Thread W owns
// chunk W's diagonal block in its own m[] registers and resolves the
// 32 bits serially; one barrier per chunk (double-buffered broadcast).
// ------------------------------------------------------------------
__global__ void head_kernel() {
    __shared__ unsigned int s_hw[2];
    const int tid = threadIdx.x;
    unsigned int remv = 0;
    unsigned int m[32];

    // prefetch chunk 0: m[b] = row b, word tid
    {
        const unsigned int* p = &g_mask[tid];
#pragma unroll
        for (int b = 0; b < 32; b++) m[b] = p[b * NW];
    }

    for (int W = 0; W < NW; W++) {
        // prefetch chunk W+1 (overlaps resolve + OR below)
        unsigned int mn[32];
        if (W + 1 < NW) {
            const unsigned int* p = &g_mask[(W + 1) * 32 * NW + tid];
#pragma unroll
            for (int b = 0; b < 32; b++) mn[b] = p[b * NW];
        }

        if (tid == W) {
            // m[b] for tid==W is exactly the diagonal word of chunk W
            unsigned int sup = remv, hw = 0;
#pragma unroll
            for (int b = 0; b < 32; b++) {
                if (!((sup >> b) & 1u)) { hw |= 1u << b; sup |= m[b]; }
            }
            remv = sup;
            s_hw[W & 1] = hw;
            g_head[W] = hw;
        }
        __syncthreads();

        unsigned int hw = s_hw[W & 1];
        if (tid > W) {
#pragma unroll
            for (int b = 0; b < 32; b++)
                if ((hw >> b) & 1u) remv |= m[b];
        }
#pragma unroll
        for (int b = 0; b < 32; b++) m[b] = mn[b];
        // no second barrier: next chunk's writer uses the other s_hw slot,
        // and the reuse of this slot (W+2) is fenced by chunk W+1's barrier.
    }
}

// ------------------------------------------------------------------
// K4: warp per row: cluster[j] = first set bit of (row[j] & heads).
// 32 words per ballot round, early exit (guaranteed to hit by word j/32,
// since head rows have their own diagonal bit set). Lane 0 does atomics.
// ------------------------------------------------------------------
__global__ void cluster_kernel() {
    __shared__ unsigned int s_head[NW];
    const int tid = threadIdx.x;
    if (tid < NW) s_head[tid] = g_head[tid];
    __syncthreads();

    const int lane = tid & 31;
    const int row  = blockIdx.x * 8 + (tid >> 5);
    const unsigned int* r = &g_mask[row * NW];

    int c = row;
    for (int w0 = 0; w0 < NW; w0 += 32) {
        unsigned int v = r[w0 + lane] & s_head[w0 + lane];
        unsigned int ball = __ballot_sync(0xffffffffu, v != 0u);
        if (ball) {
            int l0 = __ffs(ball) - 1;
            unsigned int vv = __shfl_sync(0xffffffffu, v, l0);
            c = (w0 + l0) * 32 + (__ffs(vv) - 1);
            break;
        }
    }

    if (lane == 0) {
        g_cluster[row] = c;
        atomicAdd(&g_counts[c], 1);
        atomicAdd(&g_prob[c], g_score[row]);
        atomicMax(&g_y2bits[c], __float_as_int(g_box[row].w));  // y2 >= 0
    }
}

// ------------------------------------------------------------------
// K5: first = segment_min over candidates (y2 >= segment max)
// ------------------------------------------------------------------
__global__ void first_kernel() {
    const int j = blockIdx.x * blockDim.x + threadIdx.x;
    const int c = g_cluster[j];
    float y2 = g_box[j].w;
    float m  = __int_as_float(g_y2bits[c]);
    if (y2 >= m) atomicMin(&g_first[c], j);
}

// ------------------------------------------------------------------
// K6: keep + output. out rows (N,5) float, then keep (N) as 0/1 float.
// ------------------------------------------------------------------
__global__ void out_kernel(float* __restrict__ out, int out_size,
                           const int* __restrict__ nm_ptr) {
    const int j = blockIdx.x * blockDim.x + threadIdx.x;
    const int nm = *nm_ptr;
    const int c = g_cluster[j];
    bool keep = (g_first[c] == j) &&
                ((float)g_counts[c] >= (float)nm / 3.0f);
    float4 bb = g_box[j];
    float so = g_prob[c] / (float)nm;
    float v0 = 0.0f, v1 = 0.0f, v2 = 0.0f, v3 = 0.0f, v4 = 0.0f;
    if (keep) { v0 = bb.x; v1 = bb.y; v2 = bb.z; v3 = bb.w; v4 = so; }
    out[5 * j + 0] = v0;
    out[5 * j + 1] = v1;
    out[5 * j + 2] = v2;
    out[5 * j + 3] = v3;
    out[5 * j + 4] = v4;
    if (out_size >= 6 * N)
        out[5 * N + j] = keep ? 1.0f : 0.0f;
}

// ------------------------------------------------------------------
extern "C" void kernel_launch(void* const* d_in, const int* in_sizes, int n_in,
                              void* d_out, int out_size) {
    const float* boxes  = (const float*)d_in[0];
    const float* scores = (const float*)d_in[1];
    const int*   nm     = (const int*)d_in[2];

    cudaFuncSetAttribute(sort_kernel,
                         cudaFuncAttributeMaxDynamicSharedMemorySize, 65536);

    sort_kernel<<<1, 1024, 65536>>>(boxes, scores);
    dim3 mgrid(4, 256);
    mask_kernel<<<mgrid, 256>>>();
    head_kernel<<<1, 256>>>();
    cluster_kernel<<<1024, 256>>>();
    first_kernel<<<32, 256>>>();
    out_kernel<<<32, 256>>>((float*)d_out, out_size, nm);
}